// round 3
// baseline (speedup 1.0000x reference)
#include <cuda_runtime.h>

#define BB 16
#define EE 128
#define CC 512
#define NCL 5
#define KITERS 9    // truncation 0.2^10/0.8 ~ 1.3e-7 << 1e-3 gate

// ---------------- device scratch (no allocations allowed) ----------------
__device__ float  g_sqdist[BB*EE*EE];   // later overwritten in-place with W
__device__ float  g_norm[BB*EE];
__device__ double g_psum[256];
__device__ double g_psq[256];
__device__ float  g_rowsum[BB*EE];
__device__ int    g_lbl64;              // 1 if labels buffer is int64

// ---------------- f32x2 packed helpers (Blackwell) ----------------
__device__ __forceinline__ unsigned long long pk2(float a, float b) {
    unsigned long long r;
    asm("mov.b64 %0, {%1,%2};" : "=l"(r) : "f"(a), "f"(b));
    return r;
}
__device__ __forceinline__ void unpk2(unsigned long long v, float& lo, float& hi) {
    asm("mov.b64 {%0,%1}, %2;" : "=f"(lo), "=f"(hi) : "l"(v));
}
__device__ __forceinline__ void fma2(unsigned long long& acc,
                                     unsigned long long a, unsigned long long b) {
    asm("fma.rn.f32x2 %0, %1, %2, %0;" : "+l"(acc) : "l"(a), "l"(b));
}
__device__ __forceinline__ unsigned long long add2(unsigned long long a,
                                                   unsigned long long b) {
    unsigned long long r;
    asm("add.rn.f32x2 %0, %1, %2;" : "=l"(r) : "l"(a), "l"(b));
    return r;
}

// ================= K0: row norms + labels dtype detection =================
// grid 256, block 256 (8 warps -> 8 rows each)
__global__ void k_norm(const float* __restrict__ x, const int* __restrict__ lab32) {
    int t = threadIdx.x;
    if (blockIdx.x == 0) {
        // int64 labels (values 0..5, little-endian) => odd 32-bit words are 0.
        __shared__ int sflag;
        if (t == 0) sflag = 0;
        __syncthreads();
        int v = 0;
        #pragma unroll
        for (int k = 0; k < 4; k++) v |= lab32[2*(t + 256*k) + 1];
        if (v) sflag = 1;
        __syncthreads();
        if (t == 0) g_lbl64 = (sflag == 0);
    }
    int r    = blockIdx.x * 8 + (t >> 5);
    int lane = t & 31;
    const float* row = x + (size_t)r * CC;
    float s = 0.f;
    #pragma unroll
    for (int k = 0; k < 16; k++) { float v = row[lane + 32*k]; s += v * v; }
    #pragma unroll
    for (int o = 16; o; o >>= 1) s += __shfl_xor_sync(0xffffffffu, s, o);
    if (lane == 0) g_norm[r] = s;
}

// ================= K1: Gram -> sq_dist + stats partials =================
// grid (4,4,16): (j-tile, i-tile, batch). block 256 = 16x16, each thread 2x2.
// float4 smem tiles (row stride 17 float4 = 68 floats) -> LDS.128 inner loop.
__global__ void k_gram(const float* __restrict__ x) {
    __shared__ float4 XI[32][17];
    __shared__ float4 XJ[32][17];
    __shared__ double red[256];
    int b  = blockIdx.z;
    int ib = blockIdx.y * 32, jb = blockIdx.x * 32;
    int t  = threadIdx.x;
    int tx = t & 15, ty = t >> 4;
    const float* xb = x + (size_t)b * EE * CC;

    float a00 = 0.f, a01 = 0.f, a10 = 0.f, a11 = 0.f;
    for (int kc = 0; kc < CC; kc += 64) {
        #pragma unroll
        for (int rr = 0; rr < 2; rr++) {
            int idx = t + rr * 256;         // 0..511 over 32 rows x 16 float4
            int row = idx >> 4, c4 = idx & 15;
            XI[row][c4] = *(const float4*)&xb[(ib + row) * CC + kc + c4 * 4];
            XJ[row][c4] = *(const float4*)&xb[(jb + row) * CC + kc + c4 * 4];
        }
        __syncthreads();
        #pragma unroll
        for (int c4 = 0; c4 < 16; c4++) {
            float4 ai0 = XI[2*ty][c4],  ai1 = XI[2*ty + 1][c4];
            float4 bj0 = XJ[2*tx][c4],  bj1 = XJ[2*tx + 1][c4];
            a00 += ai0.x*bj0.x + ai0.y*bj0.y + ai0.z*bj0.z + ai0.w*bj0.w;
            a01 += ai0.x*bj1.x + ai0.y*bj1.y + ai0.z*bj1.z + ai0.w*bj1.w;
            a10 += ai1.x*bj0.x + ai1.y*bj0.y + ai1.z*bj0.z + ai1.w*bj0.w;
            a11 += ai1.x*bj1.x + ai1.y*bj1.y + ai1.z*bj1.z + ai1.w*bj1.w;
        }
        __syncthreads();
    }

    const float rsc = 0.04419417382415922f;   // 1/sqrt(512)
    int gi = ib + 2*ty, gj = jb + 2*tx;
    float ni0 = g_norm[b*EE + gi],     ni1 = g_norm[b*EE + gi + 1];
    float nj0 = g_norm[b*EE + gj],     nj1 = g_norm[b*EE + gj + 1];
    float s00 = (ni0 + nj0 - 2.f*a00) * rsc;
    float s01 = (ni0 + nj1 - 2.f*a01) * rsc;
    float s10 = (ni1 + nj0 - 2.f*a10) * rsc;
    float s11 = (ni1 + nj1 - 2.f*a11) * rsc;
    float* o = g_sqdist + (size_t)(b*EE + gi) * EE + gj;
    o[0] = s00; o[1] = s01; o[EE] = s10; o[EE + 1] = s11;

    // masked stats (mask == off-diagonal); diag hits only s00/s11 (gi==gj)
    double d0 = s00, d1 = s01, d2 = s10, d3 = s11;
    double sm, sq;
    if (gi != gj) { sm = d0 + d1 + d2 + d3; sq = d0*d0 + d1*d1 + d2*d2 + d3*d3; }
    else          { sm = d1 + d2;           sq = d1*d1 + d2*d2; }

    red[t] = sm; __syncthreads();
    for (int o2 = 128; o2; o2 >>= 1) { if (t < o2) red[t] += red[t + o2]; __syncthreads(); }
    int pidx = b * 16 + blockIdx.y * 4 + blockIdx.x;
    if (t == 0) g_psum[pidx] = red[0];
    __syncthreads();
    red[t] = sq; __syncthreads();
    for (int o2 = 128; o2; o2 >>= 1) { if (t < o2) red[t] += red[t + o2]; __syncthreads(); }
    if (t == 0) g_psq[pidx] = red[0];
}

// ================= K2: weights (in-place) + row sums =================
// grid (16 rowgroups, 16 batches), block 256 = 8 warps = 8 rows
__global__ void k_weights() {
    __shared__ double red[256];
    __shared__ float sh_inv;
    int t = threadIdx.x;

    red[t] = g_psum[t]; __syncthreads();
    for (int o = 128; o; o >>= 1) { if (t < o) red[t] += red[t + o]; __syncthreads(); }
    double S1 = red[0];
    __syncthreads();
    red[t] = g_psq[t]; __syncthreads();
    for (int o = 128; o; o >>= 1) { if (t < o) red[t] += red[t + o]; __syncthreads(); }
    if (t == 0) {
        double S2  = red[0];
        const double cnt = (double)BB * EE * (EE - 1);   // mask = off-diagonal
        double var = (S2 - S1 * S1 / cnt) / (cnt - 1.0); // Bessel (ddof=1)
        sh_inv = (float)(1.0 / sqrt(var));
    }
    __syncthreads();
    float inv = sh_inv;

    int b    = blockIdx.y;
    int i    = blockIdx.x * 8 + (t >> 5);
    int lane = t & 31;
    float rs = 0.f;
    float* rowp = g_sqdist + (size_t)(b*EE + i) * EE;
    #pragma unroll
    for (int k = 0; k < 4; k++) {
        int j = lane + 32*k;
        float w = (j == i) ? 0.f : expf(-rowp[j] * inv);
        rowp[j] = w;
        rs += w;
    }
    #pragma unroll
    for (int o = 16; o; o >>= 1) rs += __shfl_xor_sync(0xffffffffu, rs, o);
    if (lane == 0) g_rowsum[b*EE + i] = rs;
}

// ================= K3: Neumann propagation + output =================
// grid 16 (one batch per block), block 512: thread = (row i, j-quarter q)
// P = (I - aS)^-1 = sum_k (aS)^k applied to [onehot(5) | ones].
// aS row chunk (32 values) pre-packed as f32x2 pairs in registers.
// v/pbuf rows padded to 12 floats (48B) -> conflict-free LDS/STS.128.
#define VR 12
__global__ void __launch_bounds__(512, 1)
k_prop(const int* __restrict__ lab32, float* __restrict__ out) {
    __shared__ float f[EE];
    __shared__ __align__(16) float v[EE * VR];
    __shared__ __align__(16) float pbuf[3 * EE * VR];
    int b = blockIdx.x, t = threadIdx.x;
    int i = t & 127, q = t >> 7;           // q in 0..3
    int base = q * 32;

    if (t < EE) f[t] = 0.2f / (1e-4f + g_rowsum[b*EE + t]);   // alpha folded in
    __syncthreads();

    // ss[jj] packed {s,s}; s = alpha*S[i][base+jj] = W[base+jj][i]*f[base+jj]
    const float* Wb = g_sqdist + (size_t)b * EE * EE;
    unsigned long long ss[32];
    #pragma unroll
    for (int jj = 0; jj < 32; jj++) {
        float sv = Wb[(base + jj) * EE + i] * f[base + jj];
        ss[jj] = pk2(sv, sv);
    }

    unsigned long long a01 = 0ull, a23 = 0ull, a45 = 0ull;
    if (q == 0) {
        int lbl = g_lbl64 ? lab32[2*(b*EE + i)] : lab32[b*EE + i];
        float vv[6];
        #pragma unroll
        for (int c = 0; c < NCL; c++) vv[c] = (lbl == c) ? 1.f : 0.f;
        vv[5] = 1.f;   // ones column -> L1 row norm of P (P >= 0)
        a01 = pk2(vv[0], vv[1]); a23 = pk2(vv[2], vv[3]); a45 = pk2(vv[4], vv[5]);
        *(ulonglong2*)&v[i*VR]     = make_ulonglong2(a01, a23);
        *(unsigned long long*)&v[i*VR + 4] = a45;
    }
    __syncthreads();

    for (int it = 0; it < KITERS; it++) {
        unsigned long long p01 = 0ull, p23 = 0ull, p45 = 0ull;
        #pragma unroll
        for (int jj = 0; jj < 32; jj++) {
            int j = base + jj;
            ulonglong2 w = *(const ulonglong2*)&v[j*VR];
            unsigned long long w2 = *(const unsigned long long*)&v[j*VR + 4];
            fma2(p01, ss[jj], w.x); fma2(p23, ss[jj], w.y); fma2(p45, ss[jj], w2);
        }
        if (q) {
            float* pb = &pbuf[((q - 1) * EE + i) * VR];
            *(ulonglong2*)pb = make_ulonglong2(p01, p23);
            *(unsigned long long*)(pb + 4) = p45;
        }
        __syncthreads();
        if (q == 0) {
            #pragma unroll
            for (int k = 0; k < 3; k++) {
                const float* pb = &pbuf[(k * EE + i) * VR];
                ulonglong2 r = *(const ulonglong2*)pb;
                unsigned long long r2 = *(const unsigned long long*)(pb + 4);
                p01 = add2(p01, r.x); p23 = add2(p23, r.y); p45 = add2(p45, r2);
            }
            a01 = add2(a01, p01); a23 = add2(a23, p23); a45 = add2(a45, p45);
            *(ulonglong2*)&v[i*VR]     = make_ulonglong2(p01, p23);
            *(unsigned long long*)&v[i*VR + 4] = p45;
        }
        __syncthreads();   // v fully updated before next iteration reads it
    }

    if (q == 0) {
        float y0, y1, y2, y3, y4, l1;
        unpk2(a01, y0, y1); unpk2(a23, y2, y3); unpk2(a45, y4, l1);
        float inv = 1.f / fmaxf(l1, 1e-12f);
        float* o = out + (size_t)(b*EE + i) * NCL;
        o[0] = logf(y0 * inv + 1e-6f);
        o[1] = logf(y1 * inv + 1e-6f);
        o[2] = logf(y2 * inv + 1e-6f);
        o[3] = logf(y3 * inv + 1e-6f);
        o[4] = logf(y4 * inv + 1e-6f);
    }
}

// ================= launcher =================
extern "C" void kernel_launch(void* const* d_in, const int* in_sizes, int n_in,
                              void* d_out, int out_size) {
    const float* x   = (const float*)d_in[0];
    const int*   lab = (const int*)d_in[1];   // int32 or int64 — detected on device
    float*       out = (float*)d_out;

    k_norm<<<256, 256>>>(x, lab);
    k_gram<<<dim3(4, 4, BB), 256>>>(x);
    k_weights<<<dim3(16, BB), 256>>>();
    k_prop<<<BB, 512>>>(lab, out);
}

// round 4
// speedup vs baseline: 1.2767x; 1.2767x over previous
#include <cuda_runtime.h>

#define BB 16
#define EE 128
#define CC 512
#define NCL 5
#define KITERS 8    // truncation 0.2^9/0.8 ~ 6.5e-7 << 1e-3 gate

// ---------------- device scratch (no allocations allowed) ----------------
__device__ float  g_part[2*BB*EE*EE];   // k-split partial Grams
__device__ float  g_sqdist[BB*EE*EE];   // scaled sq_dist, then W in-place
__device__ float  g_norm[BB*EE];
__device__ double g_psum[256];
__device__ double g_psq[256];
__device__ float  g_rowsum[BB*EE];
__device__ int    g_lbl64;              // 1 if labels buffer is int64

// ---------------- f32x2 packed helpers (Blackwell) ----------------
__device__ __forceinline__ unsigned long long pk2(float a, float b) {
    unsigned long long r;
    asm("mov.b64 %0, {%1,%2};" : "=l"(r) : "f"(a), "f"(b));
    return r;
}
__device__ __forceinline__ void unpk2(unsigned long long v, float& lo, float& hi) {
    asm("mov.b64 {%0,%1}, %2;" : "=f"(lo), "=f"(hi) : "l"(v));
}
__device__ __forceinline__ void fma2(unsigned long long& acc,
                                     unsigned long long a, unsigned long long b) {
    asm("fma.rn.f32x2 %0, %1, %2, %0;" : "+l"(acc) : "l"(a), "l"(b));
}
__device__ __forceinline__ unsigned long long add2(unsigned long long a,
                                                   unsigned long long b) {
    unsigned long long r;
    asm("add.rn.f32x2 %0, %1, %2;" : "=l"(r) : "l"(a), "l"(b));
    return r;
}

// ================= K0: row norms + labels dtype detection =================
// grid 256, block 256 (8 warps -> 8 rows each)
__global__ void k_norm(const float* __restrict__ x, const int* __restrict__ lab32) {
    int t = threadIdx.x;
    if (blockIdx.x == 0) {
        // int64 labels (values 0..5, LE) => odd 32-bit words are all 0.
        __shared__ int sflag;
        if (t == 0) sflag = 0;
        __syncthreads();
        int v = 0;
        #pragma unroll
        for (int k = 0; k < 4; k++) v |= lab32[2*(t + 256*k) + 1];
        if (v) sflag = 1;
        __syncthreads();
        if (t == 0) g_lbl64 = (sflag == 0);
    }
    int r    = blockIdx.x * 8 + (t >> 5);
    int lane = t & 31;
    const float* row = x + (size_t)r * CC;
    float s = 0.f;
    #pragma unroll
    for (int k = 0; k < 16; k++) { float v = row[lane + 32*k]; s += v * v; }
    #pragma unroll
    for (int o = 16; o; o >>= 1) s += __shfl_xor_sync(0xffffffffu, s, o);
    if (lane == 0) g_norm[r] = s;
}

// ================= K1: partial Gram, 64x64 tile, 4x4/thread, f32x2 =====
// grid (2 jt, 2 it, 32 = b*2+kc), 256 threads (16x16). k-split: 256 ch each.
// smem float2 tiles [64][32], XOR-swizzled: phys c2' = c2 ^ ((row>>2)&15)
// -> b-side reads (rows 4tx+s) hit bank (c2^tx)%16: conflict-free.
__global__ void __launch_bounds__(256) k_gram(const float* __restrict__ x) {
    __shared__ float2 sxi[64][32];
    __shared__ float2 sxj[64][32];
    int t  = threadIdx.x;
    int tx = t & 15, ty = t >> 4;
    int b  = blockIdx.z >> 1, kc = blockIdx.z & 1;
    int ib = blockIdx.y * 64, jb = blockIdx.x * 64;
    const float* xb = x + (size_t)b * EE * CC;

    unsigned long long acc[4][4];
    #pragma unroll
    for (int r = 0; r < 4; r++)
        #pragma unroll
        for (int s = 0; s < 4; s++) acc[r][s] = 0ull;

    for (int chunk = 0; chunk < 4; chunk++) {
        int ch0 = kc * 256 + chunk * 64;
        #pragma unroll
        for (int k = 0; k < 8; k++) {
            int idx = t + k * 256;           // 2048 float2 per tile
            int row = idx >> 5, c2 = idx & 31;
            int sw  = c2 ^ ((row >> 2) & 15);
            sxi[row][sw] = *(const float2*)&xb[(ib + row) * CC + ch0 + c2 * 2];
            sxj[row][sw] = *(const float2*)&xb[(jb + row) * CC + ch0 + c2 * 2];
        }
        __syncthreads();
        #pragma unroll
        for (int c2 = 0; c2 < 32; c2++) {
            unsigned long long a2[4], b2[4];
            int ca = c2 ^ ty, cb = c2 ^ tx;
            #pragma unroll
            for (int r = 0; r < 4; r++) a2[r] = *(const unsigned long long*)&sxi[4*ty + r][ca];
            #pragma unroll
            for (int s = 0; s < 4; s++) b2[s] = *(const unsigned long long*)&sxj[4*tx + s][cb];
            #pragma unroll
            for (int r = 0; r < 4; r++)
                #pragma unroll
                for (int s = 0; s < 4; s++) fma2(acc[r][s], a2[r], b2[s]);
        }
        __syncthreads();
    }

    float* dst = g_part + (size_t)((kc * BB + b) * EE + ib + 4*ty) * EE + jb + 4*tx;
    #pragma unroll
    for (int r = 0; r < 4; r++) {
        float4 o;
        float lo, hi;
        unpk2(acc[r][0], lo, hi); o.x = lo + hi;
        unpk2(acc[r][1], lo, hi); o.y = lo + hi;
        unpk2(acc[r][2], lo, hi); o.z = lo + hi;
        unpk2(acc[r][3], lo, hi); o.w = lo + hi;
        *(float4*)(dst + (size_t)r * EE) = o;
    }
}

// ================= K2: combine partials -> sq_dist + stats partials ====
// grid (16 rowgroups, 16 batches), 256 thr: warp = row, lane covers 4 cols
__global__ void k_combine() {
    __shared__ double red[256];
    int t = threadIdx.x;
    int b = blockIdx.y, rg = blockIdx.x;
    int i = rg * 8 + (t >> 5);
    int lane = t & 31;
    const float rsc = 0.04419417382415922f;   // 1/sqrt(512)
    size_t base = (size_t)(b * EE + i) * EE;
    float ni = g_norm[b*EE + i];
    double sm = 0.0, sq = 0.0;
    #pragma unroll
    for (int k = 0; k < 4; k++) {
        int j = lane + 32*k;
        float G = g_part[(size_t)(0*BB + b)*EE*EE + (size_t)i*EE + j]
                + g_part[(size_t)(1*BB + b)*EE*EE + (size_t)i*EE + j];
        float sd = (ni + g_norm[b*EE + j] - 2.f * G) * rsc;
        g_sqdist[base + j] = sd;
        if (j != i) { double d = sd; sm += d; sq += d * d; }
    }
    red[t] = sm; __syncthreads();
    for (int o = 128; o; o >>= 1) { if (t < o) red[t] += red[t + o]; __syncthreads(); }
    if (t == 0) g_psum[b * 16 + rg] = red[0];
    __syncthreads();
    red[t] = sq; __syncthreads();
    for (int o = 128; o; o >>= 1) { if (t < o) red[t] += red[t + o]; __syncthreads(); }
    if (t == 0) g_psq[b * 16 + rg] = red[0];
}

// ================= K3: weights (in-place) + row sums =================
// grid (16 rowgroups, 16 batches), block 256 = 8 warps = 8 rows
__global__ void k_weights() {
    __shared__ double red[256];
    __shared__ float sh_inv;
    int t = threadIdx.x;

    red[t] = g_psum[t]; __syncthreads();
    for (int o = 128; o; o >>= 1) { if (t < o) red[t] += red[t + o]; __syncthreads(); }
    double S1 = red[0];
    __syncthreads();
    red[t] = g_psq[t]; __syncthreads();
    for (int o = 128; o; o >>= 1) { if (t < o) red[t] += red[t + o]; __syncthreads(); }
    if (t == 0) {
        double S2  = red[0];
        const double cnt = (double)BB * EE * (EE - 1);   // mask = off-diagonal
        double var = (S2 - S1 * S1 / cnt) / (cnt - 1.0); // Bessel (ddof=1)
        sh_inv = (float)(1.0 / sqrt(var));
    }
    __syncthreads();
    float inv = sh_inv;

    int b    = blockIdx.y;
    int i    = blockIdx.x * 8 + (t >> 5);
    int lane = t & 31;
    float rs = 0.f;
    float* rowp = g_sqdist + (size_t)(b*EE + i) * EE;
    #pragma unroll
    for (int k = 0; k < 4; k++) {
        int j = lane + 32*k;
        float w = (j == i) ? 0.f : expf(-rowp[j] * inv);
        rowp[j] = w;
        rs += w;
    }
    #pragma unroll
    for (int o = 16; o; o >>= 1) rs += __shfl_xor_sync(0xffffffffu, rs, o);
    if (lane == 0) g_rowsum[b*EE + i] = rs;
}

// ================= K4: Neumann propagation + output =================
// grid 16 (one batch per block), block 1024: thread = (row i, j-octant q)
// P = (I - aS)^-1 = sum_k (aS)^k applied to [onehot(5) | ones].
#define VR 12
__global__ void __launch_bounds__(1024, 1)
k_prop(const int* __restrict__ lab32, float* __restrict__ out) {
    __shared__ float f[EE];
    __shared__ __align__(16) float v[EE * VR];
    __shared__ __align__(16) float pbuf[7 * EE * 8];
    int b = blockIdx.x, t = threadIdx.x;
    int i = t & 127, q = t >> 7;           // q in 0..7
    int base = q * 16;

    if (t < EE) f[t] = 0.2f / (1e-4f + g_rowsum[b*EE + t]);   // alpha folded in
    __syncthreads();

    // ss[jj] packed {s,s}; s = alpha*S[i][base+jj] = W[base+jj][i]*f[base+jj]
    const float* Wb = g_sqdist + (size_t)b * EE * EE;
    unsigned long long ss[16];
    #pragma unroll
    for (int jj = 0; jj < 16; jj++) {
        float sv = Wb[(base + jj) * EE + i] * f[base + jj];
        ss[jj] = pk2(sv, sv);
    }

    unsigned long long a01 = 0ull, a23 = 0ull, a45 = 0ull;
    if (q == 0) {
        int lbl = g_lbl64 ? lab32[2*(b*EE + i)] : lab32[b*EE + i];
        float vv[6];
        #pragma unroll
        for (int c = 0; c < NCL; c++) vv[c] = (lbl == c) ? 1.f : 0.f;
        vv[5] = 1.f;   // ones column -> L1 row norm of P (P >= 0)
        a01 = pk2(vv[0], vv[1]); a23 = pk2(vv[2], vv[3]); a45 = pk2(vv[4], vv[5]);
        *(ulonglong2*)&v[i*VR]     = make_ulonglong2(a01, a23);
        *(unsigned long long*)&v[i*VR + 4] = a45;
    }
    __syncthreads();

    for (int it = 0; it < KITERS; it++) {
        unsigned long long p01 = 0ull, p23 = 0ull, p45 = 0ull;
        #pragma unroll
        for (int jj = 0; jj < 16; jj++) {
            int j = base + jj;
            ulonglong2 w = *(const ulonglong2*)&v[j*VR];
            unsigned long long w2 = *(const unsigned long long*)&v[j*VR + 4];
            fma2(p01, ss[jj], w.x); fma2(p23, ss[jj], w.y); fma2(p45, ss[jj], w2);
        }
        if (q) {
            float* pb = &pbuf[((q - 1) * EE + i) * 8];
            *(ulonglong2*)pb = make_ulonglong2(p01, p23);
            *(unsigned long long*)(pb + 4) = p45;
        }
        __syncthreads();
        if (q == 0) {
            #pragma unroll
            for (int k = 0; k < 7; k++) {
                const float* pb = &pbuf[(k * EE + i) * 8];
                ulonglong2 r = *(const ulonglong2*)pb;
                unsigned long long r2 = *(const unsigned long long*)(pb + 4);
                p01 = add2(p01, r.x); p23 = add2(p23, r.y); p45 = add2(p45, r2);
            }
            a01 = add2(a01, p01); a23 = add2(a23, p23); a45 = add2(a45, p45);
            *(ulonglong2*)&v[i*VR]     = make_ulonglong2(p01, p23);
            *(unsigned long long*)&v[i*VR + 4] = p45;
        }
        __syncthreads();   // v fully updated before next iteration reads it
    }

    if (q == 0) {
        float y0, y1, y2, y3, y4, l1;
        unpk2(a01, y0, y1); unpk2(a23, y2, y3); unpk2(a45, y4, l1);
        float inv = 1.f / fmaxf(l1, 1e-12f);
        float* o = out + (size_t)(b*EE + i) * NCL;
        o[0] = logf(y0 * inv + 1e-6f);
        o[1] = logf(y1 * inv + 1e-6f);
        o[2] = logf(y2 * inv + 1e-6f);
        o[3] = logf(y3 * inv + 1e-6f);
        o[4] = logf(y4 * inv + 1e-6f);
    }
}

// ================= launcher =================
extern "C" void kernel_launch(void* const* d_in, const int* in_sizes, int n_in,
                              void* d_out, int out_size) {
    const float* x   = (const float*)d_in[0];
    const int*   lab = (const int*)d_in[1];   // int32 or int64 — detected on device
    float*       out = (float*)d_out;

    k_norm<<<256, 256>>>(x, lab);
    k_gram<<<dim3(2, 2, 32), 256>>>(x);
    k_combine<<<dim3(16, BB), 256>>>();
    k_weights<<<dim3(16, BB), 256>>>();
    k_prop<<<BB, 1024>>>(lab, out);
}

// round 7
// speedup vs baseline: 1.3505x; 1.0578x over previous
#include <cuda_runtime.h>

#define BB 16
#define EE 128
#define CC 512
#define NCL 5
#define KITERS 8    // truncation 0.2^9/0.8 ~ 6.5e-7 << 1e-3 gate

// ---------------- device scratch (no allocations allowed) ----------------
__device__ float  g_part[2*BB*EE*EE];   // k-split partial Grams
__device__ float  g_sqdist[BB*EE*EE];   // scaled sq_dist matrix
__device__ double g_psum[128];
__device__ double g_psq[128];
__device__ int    g_lbl64;              // 1 if labels buffer is int64

// ---------------- f32x2 packed helpers (Blackwell) ----------------
__device__ __forceinline__ unsigned long long pk2(float a, float b) {
    unsigned long long r;
    asm("mov.b64 %0, {%1,%2};" : "=l"(r) : "f"(a), "f"(b));
    return r;
}
__device__ __forceinline__ void unpk2(unsigned long long v, float& lo, float& hi) {
    asm("mov.b64 {%0,%1}, %2;" : "=f"(lo), "=f"(hi) : "l"(v));
}
__device__ __forceinline__ void fma2(unsigned long long& acc,
                                     unsigned long long a, unsigned long long b) {
    asm("fma.rn.f32x2 %0, %1, %2, %0;" : "+l"(acc) : "l"(a), "l"(b));
}
__device__ __forceinline__ unsigned long long add2(unsigned long long a,
                                                   unsigned long long b) {
    unsigned long long r;
    asm("add.rn.f32x2 %0, %1, %2;" : "=l"(r) : "l"(a), "l"(b));
    return r;
}

// ================= K1: partial Gram, 64x64 tile, 4x4/thread, f32x2 =====
// grid (2 jt, 2 it, 32 = b*2+kc), 256 threads (16x16). k-split: 256 ch each.
// smem float2 tiles [64][32], XOR-swizzled: phys c2' = c2 ^ ((row>>2)&15)
__global__ void __launch_bounds__(256) k_gram(const float* __restrict__ x,
                                              const int* __restrict__ lab32) {
    __shared__ float2 sxi[64][32];
    __shared__ float2 sxj[64][32];
    int t  = threadIdx.x;
    int tx = t & 15, ty = t >> 4;
    int b  = blockIdx.z >> 1, kc = blockIdx.z & 1;
    int ib = blockIdx.y * 64, jb = blockIdx.x * 64;
    const float* xb = x + (size_t)b * EE * CC;

    // labels dtype detection (block 0 only): int64 => odd 32-bit words all 0
    if (blockIdx.x == 0 && blockIdx.y == 0 && blockIdx.z == 0) {
        __shared__ int sflag;
        if (t == 0) sflag = 0;
        __syncthreads();
        int v = 0;
        #pragma unroll
        for (int k = 0; k < 4; k++) v |= lab32[2*(t + 256*k) + 1];
        if (v) sflag = 1;
        __syncthreads();
        if (t == 0) g_lbl64 = (sflag == 0);
        __syncthreads();
    }

    unsigned long long acc[4][4];
    #pragma unroll
    for (int r = 0; r < 4; r++)
        #pragma unroll
        for (int s = 0; s < 4; s++) acc[r][s] = 0ull;

    for (int chunk = 0; chunk < 4; chunk++) {
        int ch0 = kc * 256 + chunk * 64;
        #pragma unroll
        for (int k = 0; k < 8; k++) {
            int idx = t + k * 256;           // 2048 float2 per tile
            int row = idx >> 5, c2 = idx & 31;
            int sw  = c2 ^ ((row >> 2) & 15);
            sxi[row][sw] = *(const float2*)&xb[(ib + row) * CC + ch0 + c2 * 2];
            sxj[row][sw] = *(const float2*)&xb[(jb + row) * CC + ch0 + c2 * 2];
        }
        __syncthreads();
        #pragma unroll
        for (int c2 = 0; c2 < 32; c2++) {
            unsigned long long a2[4], b2[4];
            int ca = c2 ^ ty, cb = c2 ^ tx;
            #pragma unroll
            for (int r = 0; r < 4; r++) a2[r] = *(const unsigned long long*)&sxi[4*ty + r][ca];
            #pragma unroll
            for (int s = 0; s < 4; s++) b2[s] = *(const unsigned long long*)&sxj[4*tx + s][cb];
            #pragma unroll
            for (int r = 0; r < 4; r++)
                #pragma unroll
                for (int s = 0; s < 4; s++) fma2(acc[r][s], a2[r], b2[s]);
        }
        __syncthreads();
    }

    float* dst = g_part + (size_t)((kc * BB + b) * EE + ib + 4*ty) * EE + jb + 4*tx;
    #pragma unroll
    for (int r = 0; r < 4; r++) {
        float4 o;
        float lo, hi;
        unpk2(acc[r][0], lo, hi); o.x = lo + hi;
        unpk2(acc[r][1], lo, hi); o.y = lo + hi;
        unpk2(acc[r][2], lo, hi); o.z = lo + hi;
        unpk2(acc[r][3], lo, hi); o.w = lo + hi;
        *(float4*)(dst + (size_t)r * EE) = o;
    }
}

// ================= K2: combine partials -> sq_dist + stats partials ====
// grid (8 rowgroups, 16 batches) = 128 blocks, 512 thr: warp = row.
__global__ void __launch_bounds__(512) k_sd() {
    __shared__ float  diag[EE];
    __shared__ double sred[16], qred[16];
    int t = threadIdx.x;
    int b = blockIdx.y, rg = blockIdx.x;
    int w = t >> 5, lane = t & 31;
    int i = rg * 16 + w;
    const float rsc = 0.04419417382415922f;   // 1/sqrt(512)

    const float* gp0 = g_part + (size_t)b * EE * EE;
    const float* gp1 = g_part + (size_t)(BB + b) * EE * EE;

    if (t < EE) diag[t] = gp0[(size_t)t * EE + t] + gp1[(size_t)t * EE + t];
    __syncthreads();

    float  ni = diag[i];
    double sm = 0.0, sq = 0.0;
    float* rowp = g_sqdist + (size_t)(b * EE + i) * EE;
    #pragma unroll
    for (int k = 0; k < 4; k++) {
        int j = lane + 32*k;
        float G = gp0[(size_t)i * EE + j] + gp1[(size_t)i * EE + j];
        float sd = (ni + diag[j] - 2.f * G) * rsc;
        rowp[j] = sd;
        if (j != i) { double d = sd; sm += d; sq += d * d; }
    }
    #pragma unroll
    for (int o = 16; o; o >>= 1) {
        sm += __shfl_xor_sync(0xffffffffu, sm, o);
        sq += __shfl_xor_sync(0xffffffffu, sq, o);
    }
    if (lane == 0) { sred[w] = sm; qred[w] = sq; }
    __syncthreads();
    if (w == 0) {
        double s2 = (lane < 16) ? sred[lane] : 0.0;
        double q2 = (lane < 16) ? qred[lane] : 0.0;
        #pragma unroll
        for (int o = 8; o; o >>= 1) {
            s2 += __shfl_xor_sync(0xffffffffu, s2, o);
            q2 += __shfl_xor_sync(0xffffffffu, q2, o);
        }
        if (lane == 0) { g_psum[b * 8 + rg] = s2; g_psq[b * 8 + rg] = q2; }
    }
}

// ================= K3: stats + weights + rowsum + Neumann + output =====
// grid 16 (one batch per block), block 1024: thread = (row i, j-octant q).
// Prologue: warp0 reduces the 128 stat partials -> inv std; each thread
// computes its 16 W entries inline (exp) and the block reduces row sums
// (thread (i,q) holds W[base+jj][i]; sum over i == row sum, W symmetric).
#define VR 12
__global__ void __launch_bounds__(1024, 1)
k_prop(const int* __restrict__ lab32, float* __restrict__ out) {
    __shared__ __align__(16) float f[EE];
    __shared__ float sh_inv;
    __shared__ __align__(16) float rs_part[EE * 4];
    __shared__ __align__(16) float v[EE * VR];
    __shared__ __align__(16) float pbuf[7 * EE * 8];
    int b = blockIdx.x, t = threadIdx.x;
    int i = t & 127, q = t >> 7;           // q in 0..7
    int lane = t & 31, wq = (t >> 5) & 3;  // warp index within q-group
    int base = q * 16;

    // ---- 1/std from the 128 double partials (warp 0) ----
    if (t < 32) {
        double s2 = g_psum[t] + g_psum[t + 32] + g_psum[t + 64] + g_psum[t + 96];
        double q2 = g_psq[t]  + g_psq[t + 32]  + g_psq[t + 64]  + g_psq[t + 96];
        #pragma unroll
        for (int o = 16; o; o >>= 1) {
            s2 += __shfl_xor_sync(0xffffffffu, s2, o);
            q2 += __shfl_xor_sync(0xffffffffu, q2, o);
        }
        if (t == 0) {
            const double cnt = (double)BB * EE * (EE - 1);     // mask = off-diagonal
            double var = (q2 - s2 * s2 / cnt) / (cnt - 1.0);   // Bessel (ddof=1)
            sh_inv = (float)(1.0 / sqrt(var));
        }
    }
    __syncthreads();
    float inv = sh_inv;

    // ---- W entries for rows base..base+15, column i ----
    const float* Sb = g_sqdist + (size_t)b * EE * EE;
    float wv[16];
    #pragma unroll
    for (int jj = 0; jj < 16; jj++) {
        int j = base + jj;
        float sd = Sb[(size_t)j * EE + i];
        wv[jj] = (j == i) ? 0.f : expf(-sd * inv);
    }

    // ---- row sums: reduce wv over i (32 lanes, then 4 warps per q) ----
    #pragma unroll
    for (int jj = 0; jj < 16; jj++) {
        float r = wv[jj];
        #pragma unroll
        for (int o = 16; o; o >>= 1) r += __shfl_xor_sync(0xffffffffu, r, o);
        if (lane == 0) rs_part[(base + jj) * 4 + wq] = r;
    }
    __syncthreads();
    if (t < EE) {
        float4 p = *(const float4*)&rs_part[t * 4];
        f[t] = 0.2f / (1e-4f + (p.x + p.y + p.z + p.w));   // alpha folded in
    }
    __syncthreads();

    // ss[jj] packed {s,s}; s = alpha*S[i][base+jj] = W[base+jj][i]*f[base+jj]
    unsigned long long ss[16];
    #pragma unroll
    for (int jj = 0; jj < 16; jj++) {
        float sv = wv[jj] * f[base + jj];
        ss[jj] = pk2(sv, sv);
    }

    unsigned long long a01 = 0ull, a23 = 0ull, a45 = 0ull;
    if (q == 0) {
        int lbl = g_lbl64 ? lab32[2*(b*EE + i)] : lab32[b*EE + i];
        float vv[6];
        #pragma unroll
        for (int c = 0; c < NCL; c++) vv[c] = (lbl == c) ? 1.f : 0.f;
        vv[5] = 1.f;   // ones column -> L1 row norm of P (P >= 0)
        a01 = pk2(vv[0], vv[1]); a23 = pk2(vv[2], vv[3]); a45 = pk2(vv[4], vv[5]);
        *(ulonglong2*)&v[i*VR]     = make_ulonglong2(a01, a23);
        *(unsigned long long*)&v[i*VR + 4] = a45;
    }
    __syncthreads();

    for (int it = 0; it < KITERS; it++) {
        unsigned long long p01 = 0ull, p23 = 0ull, p45 = 0ull;
        #pragma unroll
        for (int jj = 0; jj < 16; jj++) {
            int j = base + jj;
            ulonglong2 wvd = *(const ulonglong2*)&v[j*VR];
            unsigned long long w2 = *(const unsigned long long*)&v[j*VR + 4];
            fma2(p01, ss[jj], wvd.x); fma2(p23, ss[jj], wvd.y); fma2(p45, ss[jj], w2);
        }
        if (q) {
            float* pb = &pbuf[((q - 1) * EE + i) * 8];
            *(ulonglong2*)pb = make_ulonglong2(p01, p23);
            *(unsigned long long*)(pb + 4) = p45;
        }
        __syncthreads();
        if (q == 0) {
            #pragma unroll
            for (int k = 0; k < 7; k++) {
                const float* pb = &pbuf[(k * EE + i) * 8];
                ulonglong2 r = *(const ulonglong2*)pb;
                unsigned long long r2 = *(const unsigned long long*)(pb + 4);
                p01 = add2(p01, r.x); p23 = add2(p23, r.y); p45 = add2(p45, r2);
            }
            a01 = add2(a01, p01); a23 = add2(a23, p23); a45 = add2(a45, p45);
            *(ulonglong2*)&v[i*VR]     = make_ulonglong2(p01, p23);
            *(unsigned long long*)&v[i*VR + 4] = p45;
        }
        __syncthreads();   // v fully updated before next iteration reads it
    }

    if (q == 0) {
        float y0, y1, y2, y3, y4, l1;
        unpk2(a01, y0, y1); unpk2(a23, y2, y3); unpk2(a45, y4, l1);
        float invl = 1.f / fmaxf(l1, 1e-12f);
        float* o = out + (size_t)(b*EE + i) * NCL;
        o[0] = logf(y0 * invl + 1e-6f);
        o[1] = logf(y1 * invl + 1e-6f);
        o[2] = logf(y2 * invl + 1e-6f);
        o[3] = logf(y3 * invl + 1e-6f);
        o[4] = logf(y4 * invl + 1e-6f);
    }
}

// ================= launcher =================
extern "C" void kernel_launch(void* const* d_in, const int* in_sizes, int n_in,
                              void* d_out, int out_size) {
    const float* x   = (const float*)d_in[0];
    const int*   lab = (const int*)d_in[1];   // int32 or int64 — detected on device
    float*       out = (float*)d_out;

    k_gram<<<dim3(2, 2, 32), 256>>>(x, lab);
    k_sd<<<dim3(8, BB), 512>>>();
    k_prop<<<BB, 1024>>>(lab, out);
}

// round 8
// speedup vs baseline: 1.3529x; 1.0018x over previous
#include <cuda_runtime.h>

#define BB 16
#define EE 128
#define CC 512
#define NCL 5
#define KITERS 8    // truncation 0.2^9/0.8 ~ 6.5e-7 << 1e-3 gate

// ---------------- device scratch (no allocations allowed) ----------------
__device__ float  g_part[4*BB*EE*EE];   // 4-way k-split partial Grams
__device__ float  g_sqdist[BB*EE*EE];   // scaled sq_dist matrix
__device__ double g_psum[128];
__device__ double g_psq[128];
__device__ int    g_lbl64;              // 1 if labels buffer is int64

// ---------------- f32x2 packed helpers (Blackwell) ----------------
__device__ __forceinline__ unsigned long long pk2(float a, float b) {
    unsigned long long r;
    asm("mov.b64 %0, {%1,%2};" : "=l"(r) : "f"(a), "f"(b));
    return r;
}
__device__ __forceinline__ void unpk2(unsigned long long v, float& lo, float& hi) {
    asm("mov.b64 {%0,%1}, %2;" : "=f"(lo), "=f"(hi) : "l"(v));
}
__device__ __forceinline__ void fma2(unsigned long long& acc,
                                     unsigned long long a, unsigned long long b) {
    asm("fma.rn.f32x2 %0, %1, %2, %0;" : "+l"(acc) : "l"(a), "l"(b));
}
__device__ __forceinline__ unsigned long long add2(unsigned long long a,
                                                   unsigned long long b) {
    unsigned long long r;
    asm("add.rn.f32x2 %0, %1, %2;" : "=l"(r) : "l"(a), "l"(b));
    return r;
}

// ================= K1: partial Gram, 64x64 tile, 4x4/thread, f32x2 =====
// grid (2 jt, 2 it, 64 = b*4+kc), 256 threads (16x16). k-split: 128 ch each
// -> 256 blocks (~2/SM, 4 warps/SMSP) to cover FMA+LDS latency.
// smem float2 tiles [64][32], XOR-swizzled: phys c2' = c2 ^ ((row>>2)&15)
__global__ void __launch_bounds__(256) k_gram(const float* __restrict__ x,
                                              const int* __restrict__ lab32) {
    __shared__ float2 sxi[64][32];
    __shared__ float2 sxj[64][32];
    int t  = threadIdx.x;
    int tx = t & 15, ty = t >> 4;
    int b  = blockIdx.z >> 2, kc = blockIdx.z & 3;
    int ib = blockIdx.y * 64, jb = blockIdx.x * 64;
    const float* xb = x + (size_t)b * EE * CC;

    // labels dtype detection (block 0 only): int64 => odd 32-bit words all 0
    if (blockIdx.x == 0 && blockIdx.y == 0 && blockIdx.z == 0) {
        __shared__ int sflag;
        if (t == 0) sflag = 0;
        __syncthreads();
        int v = 0;
        #pragma unroll
        for (int k = 0; k < 4; k++) v |= lab32[2*(t + 256*k) + 1];
        if (v) sflag = 1;
        __syncthreads();
        if (t == 0) g_lbl64 = (sflag == 0);
        __syncthreads();
    }

    unsigned long long acc[4][4];
    #pragma unroll
    for (int r = 0; r < 4; r++)
        #pragma unroll
        for (int s = 0; s < 4; s++) acc[r][s] = 0ull;

    #pragma unroll
    for (int chunk = 0; chunk < 2; chunk++) {
        int ch0 = kc * 128 + chunk * 64;
        #pragma unroll
        for (int k = 0; k < 8; k++) {
            int idx = t + k * 256;           // 2048 float2 per tile
            int row = idx >> 5, c2 = idx & 31;
            int sw  = c2 ^ ((row >> 2) & 15);
            sxi[row][sw] = *(const float2*)&xb[(ib + row) * CC + ch0 + c2 * 2];
            sxj[row][sw] = *(const float2*)&xb[(jb + row) * CC + ch0 + c2 * 2];
        }
        __syncthreads();
        #pragma unroll
        for (int c2 = 0; c2 < 32; c2++) {
            unsigned long long a2[4], b2[4];
            int ca = c2 ^ ty, cb = c2 ^ tx;
            #pragma unroll
            for (int r = 0; r < 4; r++) a2[r] = *(const unsigned long long*)&sxi[4*ty + r][ca];
            #pragma unroll
            for (int s = 0; s < 4; s++) b2[s] = *(const unsigned long long*)&sxj[4*tx + s][cb];
            #pragma unroll
            for (int r = 0; r < 4; r++)
                #pragma unroll
                for (int s = 0; s < 4; s++) fma2(acc[r][s], a2[r], b2[s]);
        }
        __syncthreads();
    }

    float* dst = g_part + (size_t)((kc * BB + b) * EE + ib + 4*ty) * EE + jb + 4*tx;
    #pragma unroll
    for (int r = 0; r < 4; r++) {
        float4 o;
        float lo, hi;
        unpk2(acc[r][0], lo, hi); o.x = lo + hi;
        unpk2(acc[r][1], lo, hi); o.y = lo + hi;
        unpk2(acc[r][2], lo, hi); o.z = lo + hi;
        unpk2(acc[r][3], lo, hi); o.w = lo + hi;
        *(float4*)(dst + (size_t)r * EE) = o;
    }
}

// ================= K2: combine partials -> sq_dist + stats partials ====
// grid (8 rowgroups, 16 batches) = 128 blocks, 512 thr: warp = row.
__global__ void __launch_bounds__(512) k_sd() {
    __shared__ float  diag[EE];
    __shared__ double sred[16], qred[16];
    int t = threadIdx.x;
    int b = blockIdx.y, rg = blockIdx.x;
    int w = t >> 5, lane = t & 31;
    int i = rg * 16 + w;
    const float rsc = 0.04419417382415922f;   // 1/sqrt(512)

    const float* gp0 = g_part + (size_t)(0*BB + b) * EE * EE;
    const float* gp1 = g_part + (size_t)(1*BB + b) * EE * EE;
    const float* gp2 = g_part + (size_t)(2*BB + b) * EE * EE;
    const float* gp3 = g_part + (size_t)(3*BB + b) * EE * EE;

    if (t < EE) {
        size_t d = (size_t)t * EE + t;
        diag[t] = (gp0[d] + gp1[d]) + (gp2[d] + gp3[d]);
    }
    __syncthreads();

    float  ni = diag[i];
    double sm = 0.0, sq = 0.0;
    float* rowp = g_sqdist + (size_t)(b * EE + i) * EE;
    #pragma unroll
    for (int k = 0; k < 4; k++) {
        int j = lane + 32*k;
        size_t off = (size_t)i * EE + j;
        float G = (gp0[off] + gp1[off]) + (gp2[off] + gp3[off]);
        float sd = (ni + diag[j] - 2.f * G) * rsc;
        rowp[j] = sd;
        if (j != i) { double d = sd; sm += d; sq += d * d; }
    }
    #pragma unroll
    for (int o = 16; o; o >>= 1) {
        sm += __shfl_xor_sync(0xffffffffu, sm, o);
        sq += __shfl_xor_sync(0xffffffffu, sq, o);
    }
    if (lane == 0) { sred[w] = sm; qred[w] = sq; }
    __syncthreads();
    if (w == 0) {
        double s2 = (lane < 16) ? sred[lane] : 0.0;
        double q2 = (lane < 16) ? qred[lane] : 0.0;
        #pragma unroll
        for (int o = 8; o; o >>= 1) {
            s2 += __shfl_xor_sync(0xffffffffu, s2, o);
            q2 += __shfl_xor_sync(0xffffffffu, q2, o);
        }
        if (lane == 0) { g_psum[b * 8 + rg] = s2; g_psq[b * 8 + rg] = q2; }
    }
}

// ================= K3: stats + weights + rowsum + Neumann + output =====
// grid 16 (one batch per block), block 1024: thread = (row i, j-octant q).
#define VR 12
__global__ void __launch_bounds__(1024, 1)
k_prop(const int* __restrict__ lab32, float* __restrict__ out) {
    __shared__ __align__(16) float f[EE];
    __shared__ float sh_inv;
    __shared__ __align__(16) float rs_part[EE * 4];
    __shared__ __align__(16) float v[EE * VR];
    __shared__ __align__(16) float pbuf[7 * EE * 8];
    int b = blockIdx.x, t = threadIdx.x;
    int i = t & 127, q = t >> 7;           // q in 0..7
    int lane = t & 31, wq = (t >> 5) & 3;  // warp index within q-group
    int base = q * 16;

    // ---- 1/std from the 128 double partials (warp 0) ----
    if (t < 32) {
        double s2 = g_psum[t] + g_psum[t + 32] + g_psum[t + 64] + g_psum[t + 96];
        double q2 = g_psq[t]  + g_psq[t + 32]  + g_psq[t + 64]  + g_psq[t + 96];
        #pragma unroll
        for (int o = 16; o; o >>= 1) {
            s2 += __shfl_xor_sync(0xffffffffu, s2, o);
            q2 += __shfl_xor_sync(0xffffffffu, q2, o);
        }
        if (t == 0) {
            const double cnt = (double)BB * EE * (EE - 1);     // mask = off-diagonal
            double var = (q2 - s2 * s2 / cnt) / (cnt - 1.0);   // Bessel (ddof=1)
            sh_inv = (float)(1.0 / sqrt(var));
        }
    }
    __syncthreads();
    float inv = sh_inv;

    // ---- W entries for rows base..base+15, column i ----
    const float* Sb = g_sqdist + (size_t)b * EE * EE;
    float wv[16];
    #pragma unroll
    for (int jj = 0; jj < 16; jj++) {
        int j = base + jj;
        float sd = Sb[(size_t)j * EE + i];
        wv[jj] = (j == i) ? 0.f : expf(-sd * inv);
    }

    // ---- row sums: reduce wv over i (32 lanes, then 4 warps per q) ----
    #pragma unroll
    for (int jj = 0; jj < 16; jj++) {
        float r = wv[jj];
        #pragma unroll
        for (int o = 16; o; o >>= 1) r += __shfl_xor_sync(0xffffffffu, r, o);
        if (lane == 0) rs_part[(base + jj) * 4 + wq] = r;
    }
    __syncthreads();
    if (t < EE) {
        float4 p = *(const float4*)&rs_part[t * 4];
        f[t] = 0.2f / (1e-4f + (p.x + p.y + p.z + p.w));   // alpha folded in
    }
    __syncthreads();

    // ss[jj] packed {s,s}; s = alpha*S[i][base+jj] = W[base+jj][i]*f[base+jj]
    unsigned long long ss[16];
    #pragma unroll
    for (int jj = 0; jj < 16; jj++) {
        float sv = wv[jj] * f[base + jj];
        ss[jj] = pk2(sv, sv);
    }

    unsigned long long a01 = 0ull, a23 = 0ull, a45 = 0ull;
    if (q == 0) {
        int lbl = g_lbl64 ? lab32[2*(b*EE + i)] : lab32[b*EE + i];
        float vv[6];
        #pragma unroll
        for (int c = 0; c < NCL; c++) vv[c] = (lbl == c) ? 1.f : 0.f;
        vv[5] = 1.f;   // ones column -> L1 row norm of P (P >= 0)
        a01 = pk2(vv[0], vv[1]); a23 = pk2(vv[2], vv[3]); a45 = pk2(vv[4], vv[5]);
        *(ulonglong2*)&v[i*VR]     = make_ulonglong2(a01, a23);
        *(unsigned long long*)&v[i*VR + 4] = a45;
    }
    __syncthreads();

    for (int it = 0; it < KITERS; it++) {
        unsigned long long p01 = 0ull, p23 = 0ull, p45 = 0ull;
        #pragma unroll
        for (int jj = 0; jj < 16; jj++) {
            int j = base + jj;
            ulonglong2 wvd = *(const ulonglong2*)&v[j*VR];
            unsigned long long w2 = *(const unsigned long long*)&v[j*VR + 4];
            fma2(p01, ss[jj], wvd.x); fma2(p23, ss[jj], wvd.y); fma2(p45, ss[jj], w2);
        }
        if (q) {
            float* pb = &pbuf[((q - 1) * EE + i) * 8];
            *(ulonglong2*)pb = make_ulonglong2(p01, p23);
            *(unsigned long long*)(pb + 4) = p45;
        }
        __syncthreads();
        if (q == 0) {
            #pragma unroll
            for (int k = 0; k < 7; k++) {
                const float* pb = &pbuf[(k * EE + i) * 8];
                ulonglong2 r = *(const ulonglong2*)pb;
                unsigned long long r2 = *(const unsigned long long*)(pb + 4);
                p01 = add2(p01, r.x); p23 = add2(p23, r.y); p45 = add2(p45, r2);
            }
            a01 = add2(a01, p01); a23 = add2(a23, p23); a45 = add2(a45, p45);
            *(ulonglong2*)&v[i*VR]     = make_ulonglong2(p01, p23);
            *(unsigned long long*)&v[i*VR + 4] = p45;
        }
        __syncthreads();   // v fully updated before next iteration reads it
    }

    if (q == 0) {
        float y0, y1, y2, y3, y4, l1;
        unpk2(a01, y0, y1); unpk2(a23, y2, y3); unpk2(a45, y4, l1);
        float invl = 1.f / fmaxf(l1, 1e-12f);
        float* o = out + (size_t)(b*EE + i) * NCL;
        o[0] = logf(y0 * invl + 1e-6f);
        o[1] = logf(y1 * invl + 1e-6f);
        o[2] = logf(y2 * invl + 1e-6f);
        o[3] = logf(y3 * invl + 1e-6f);
        o[4] = logf(y4 * invl + 1e-6f);
    }
}

// ================= launcher =================
extern "C" void kernel_launch(void* const* d_in, const int* in_sizes, int n_in,
                              void* d_out, int out_size) {
    const float* x   = (const float*)d_in[0];
    const int*   lab = (const int*)d_in[1];   // int32 or int64 — detected on device
    float*       out = (float*)d_out;

    k_gram<<<dim3(2, 2, 64), 256>>>(x, lab);
    k_sd<<<dim3(8, BB), 512>>>();
    k_prop<<<BB, 1024>>>(lab, out);
}